// round 15
// baseline (speedup 1.0000x reference)
#include <cuda_runtime.h>
#include <cuda_bf16.h>
#include <cuda_fp16.h>
#include <math.h>

#define Dd 64
#define Nn 8192
#define Mm 256
#define NH 32
#define DN     0.3535533905932738f   /* 64^-0.25 */
#define RATIO  0.0625f               /* 256^-0.5 */
#define REPS   6.25e-8f              /* RATIO * 1e-6 */
#define DIAGC  0.0625f               /* DN^2 * 0.5 */

typedef unsigned long long u64;

// ---------------- scratch (device globals; no allocation) ----------------
__device__ float g_smax[NH * 16];                       // per (head, slice) max raw u
__device__ float g_vsum[NH * 64];                       // R[h][d] = sum_n V
__device__ float g_kvpart[(size_t)NH * 16 * 80 * 256];  // [h*16+sl][d][m], scale exp(-Mr_sl)
__device__ __half g_kvth[(size_t)NH * 80 * 256];        // kv^T fp16 hi, [h][d][m] (d=64 -> knorm)
__device__ __half g_kvtl[(size_t)NH * 80 * 256];        // kv^T fp16 lo
__device__ __align__(16) __nv_bfloat16 g_pbh[256 * 64]; // proj*DN hi, [m][d]
__device__ __align__(16) __nv_bfloat16 g_pbl[256 * 64]; // proj*DN lo

// exp on MUFU (FMUL + MUFU.EX2)
static __device__ __forceinline__ float fexp(float x) { return __expf(x); }

// HMMA m16n8k16 bf16 -> fp32 accum
static __device__ __forceinline__ void mma16816(float c[4], const unsigned a[4],
                                                unsigned b0, unsigned b1) {
    asm volatile(
        "mma.sync.aligned.m16n8k16.row.col.f32.bf16.bf16.f32 "
        "{%0,%1,%2,%3}, {%4,%5,%6,%7}, {%8,%9}, {%0,%1,%2,%3};"
        : "+f"(c[0]), "+f"(c[1]), "+f"(c[2]), "+f"(c[3])
        : "r"(a[0]), "r"(a[1]), "r"(a[2]), "r"(a[3]), "r"(b0), "r"(b1));
}
// HMMA m16n8k16 fp16 -> fp32 accum
static __device__ __forceinline__ void mma16816h(float c[4], const unsigned a[4],
                                                 unsigned b0, unsigned b1) {
    asm volatile(
        "mma.sync.aligned.m16n8k16.row.col.f32.f16.f16.f32 "
        "{%0,%1,%2,%3}, {%4,%5,%6,%7}, {%8,%9}, {%0,%1,%2,%3};"
        : "+f"(c[0]), "+f"(c[1]), "+f"(c[2]), "+f"(c[3])
        : "r"(a[0]), "r"(a[1]), "r"(a[2]), "r"(a[3]), "r"(b0), "r"(b1));
}

static __device__ __forceinline__ unsigned h2u(__half2 h) {
    return *reinterpret_cast<unsigned*>(&h);
}

// bf16 hi/lo split, packing pairs (v0,v1) -> (hi-pair, lo-pair)
static __device__ __forceinline__ void split2(float v0, float v1, unsigned& ph, unsigned& pl) {
    __nv_bfloat16 h0 = __float2bfloat16(v0);
    __nv_bfloat16 h1 = __float2bfloat16(v1);
    __nv_bfloat16 l0 = __float2bfloat16(v0 - __bfloat162float(h0));
    __nv_bfloat16 l1 = __float2bfloat16(v1 - __bfloat162float(h1));
    ph = ((unsigned)__bfloat16_as_ushort(h1) << 16) | __bfloat16_as_ushort(h0);
    pl = ((unsigned)__bfloat16_as_ushort(l1) << 16) | __bfloat16_as_ushort(l0);
}
// fp16 hi/lo split of a pair
static __device__ __forceinline__ void split2h(float v0, float v1, unsigned& ph, unsigned& pl) {
    __half2 h = __float22half2_rn(make_float2(v0, v1));
    float2 hf = __half22float2(h);
    __half2 l = __float22half2_rn(make_float2(v0 - hf.x, v1 - hf.y));
    ph = h2u(h);  pl = h2u(l);
}

// ---------------- K0: bf16-split scaled proj ----------------
__global__ void k_init(const float* __restrict__ proj)
{
    int idx = blockIdx.x * 256 + threadIdx.x;   // 64 blocks x 256
    if (idx < 256 * 64) {
        float v = proj[idx] * DN;               // [m][d] layout preserved
        __nv_bfloat16 h = __float2bfloat16(v);
        g_pbh[idx] = h;
        g_pbl[idx] = __float2bfloat16(v - __bfloat162float(h));
    }
}

// ---------------- K_vsum: R[h][d] = sum_n V ----------------
__global__ void k_vsum(const float* __restrict__ value)
{
    __shared__ float red[8];
    const int h = blockIdx.y, d = blockIdx.x, t = threadIdx.x;
    const float4* src = (const float4*)(value + ((size_t)h * 64 + d) * Nn);
    float s = 0.0f;
    #pragma unroll
    for (int i = 0; i < 8; i++) {
        float4 v = src[t + 256 * i];
        s += (v.x + v.y) + (v.z + v.w);
    }
    #pragma unroll
    for (int o = 16; o; o >>= 1) s += __shfl_xor_sync(0xffffffffu, s, o);
    if ((t & 31) == 0) red[t >> 5] = s;
    __syncthreads();
    if (t == 0) {
        float r = 0.0f;
        #pragma unroll
        for (int w2 = 0; w2 < 8; w2++) r += red[w2];
        g_vsum[h * 64 + d] = r;
    }
}

// ---------------- K1 (fused): key proj + exp + kv accumulation -------------
// grid (16 slices, 32 heads), block 512 (16 warps).
// proj MMA swapped: A = P (m rows), B = x (tok rows) -> u[m][tok], bf16 3-term.
// E fp16 hi/lo, V fp16 hi/lo. kv MMA fp16 3-term (EhVh + ElVh + EhVl).
#define KF_XH   0
#define KF_XL   9216
#define KF_PH   18432
#define KF_PL   55296
#define KF_EH   92160
#define KF_EL   129024
#define KF_VH   165888
#define KF_VL   177408
#define KF_SQP  188928
#define KF_SQ   190976
#define KF_RED  191232
#define KF_SMEM 191296

__global__ void __launch_bounds__(512, 1) k_kv_fused(const float* __restrict__ key,
                                                     const float* __restrict__ value)
{
    extern __shared__ char smem[];
    char* Xh = smem + KF_XH;   // [64 tok][72 bf16] (144 B rows)
    char* Xl = smem + KF_XL;
    char* Ph = smem + KF_PH;   // [256 m][72 bf16]
    char* Pl = smem + KF_PL;
    char* Eh = smem + KF_EH;   // [256 m][64 tok] fp16 hi (144 B rows)
    char* El = smem + KF_EL;   // fp16 lo
    char* Vh = smem + KF_VH;   // [80 d][64 tok] fp16 hi (144 B rows)
    char* Vl = smem + KF_VL;   // fp16 lo
    float* sqp = (float*)(smem + KF_SQP);   // [64][8]
    float* sq  = (float*)(smem + KF_SQ);    // [64]
    float* red = (float*)(smem + KF_RED);   // [16]

    const int t = threadIdx.x;
    const int head = blockIdx.y;
    const int slice = blockIdx.x;

    // stage P once (bf16 planes, the A operand: rows = m)
    #pragma unroll
    for (int cc = 0; cc < 4; cc++) {
        int e = t + 512 * cc;           // < 2048
        int row = e >> 3, j = e & 7;
        *(uint4*)(Ph + row * 144 + j * 16) = ((const uint4*)g_pbh)[e];
        *(uint4*)(Pl + row * 144 + j * 16) = ((const uint4*)g_pbl)[e];
    }
    // V const rows: row 64 = fp16 1.0 hi / 0 lo (knorm), rows 65..79 = 0
    for (int e = t; e < 576; e += 512) {
        int row = 64 + e / 36, col = e % 36;
        ((unsigned*)(Vh + row * 144))[col] = (row == 64 && col < 32) ? 0x3C003C00u : 0u;
        ((unsigned*)(Vl + row * 144))[col] = 0u;
    }

    const int w = t >> 5, lane = t & 31;
    const int g = lane >> 2, tq = lane & 3;
    const int mb2 = w * 16;                 // proj: m base (0..240)
    const int mg = (w & 7) * 32;            // kv: m base (0..224)
    const int dgr = (w >> 3) * 40;          // kv: d base (0 or 40)

    float Mr = -3.0e38f;                    // running slice max of raw u
    float c2[2][5][4];
    #pragma unroll
    for (int mt = 0; mt < 2; mt++)
        #pragma unroll
        for (int dt = 0; dt < 5; dt++)
            #pragma unroll
            for (int j = 0; j < 4; j++) c2[mt][dt][j] = 0.0f;

    const float* kp = key + (size_t)head * Dd * Nn;
    const float* vp = value + (size_t)head * Dd * Nn;

    for (int ch = 0; ch < 8; ch++) {
        const int n0 = slice * 512 + ch * 64;
        __syncthreads();   // prior kv MMA reads of E/V done; prior proj reads of X done

        // stage key chunk -> Xh/Xl + partial sumsq (8 d per thread)
        {
            const int tok = t & 63, dblk = t >> 6;   // dblk in 0..7
            const float* xp = kp + n0 + tok;
            float s = 0.0f;
            #pragma unroll
            for (int i = 0; i < 4; i++) {
                int d = dblk * 8 + 2 * i;
                float v0 = xp[(size_t)d * Nn];
                float v1 = xp[(size_t)(d + 1) * Nn];
                s = fmaf(v0, v0, fmaf(v1, v1, s));
                unsigned ph, pl;
                split2(v0, v1, ph, pl);
                *(unsigned*)(Xh + tok * 144 + d * 2) = ph;
                *(unsigned*)(Xl + tok * 144 + d * 2) = pl;
            }
            sqp[tok * 8 + dblk] = s;
        }
        // stage V chunk rows 0..63 fp16 hi/lo (8 tok per thread)
        {
            int d = t >> 3, q = t & 7;
            const float* src = vp + (size_t)d * Nn + n0 + q * 8;
            float4 va = *(const float4*)(src);
            float4 vb = *(const float4*)(src + 4);
            unsigned h0, l0, h1, l1, h2, l2, h3, l3;
            split2h(va.x, va.y, h0, l0);
            split2h(va.z, va.w, h1, l1);
            split2h(vb.x, vb.y, h2, l2);
            split2h(vb.z, vb.w, h3, l3);
            *(uint4*)(Vh + d * 144 + q * 16) = make_uint4(h0, h1, h2, h3);
            *(uint4*)(Vl + d * 144 + q * 16) = make_uint4(l0, l1, l2, l3);
        }
        __syncthreads();
        if (t < 64) {
            float s = 0.0f;
            #pragma unroll
            for (int j = 0; j < 8; j++) s += sqp[t * 8 + j];
            sq[t] = s;
        }

        // proj MMA (swapped): u[m][tok], warp tile 16 m x 64 tok, bf16 3-term
        float c[8][4];
        #pragma unroll
        for (int nt = 0; nt < 8; nt++)
            #pragma unroll
            for (int j = 0; j < 4; j++) c[nt][j] = 0.0f;

        #pragma unroll
        for (int k = 0; k < 4; k++) {
            const int koff = k * 16;
            unsigned ah[4], al[4];
            ah[0] = *(const unsigned*)(Ph + (mb2 + g)     * 144 + (koff + 2*tq) * 2);
            ah[1] = *(const unsigned*)(Ph + (mb2 + g + 8) * 144 + (koff + 2*tq) * 2);
            ah[2] = *(const unsigned*)(Ph + (mb2 + g)     * 144 + (koff + 8 + 2*tq) * 2);
            ah[3] = *(const unsigned*)(Ph + (mb2 + g + 8) * 144 + (koff + 8 + 2*tq) * 2);
            al[0] = *(const unsigned*)(Pl + (mb2 + g)     * 144 + (koff + 2*tq) * 2);
            al[1] = *(const unsigned*)(Pl + (mb2 + g + 8) * 144 + (koff + 2*tq) * 2);
            al[2] = *(const unsigned*)(Pl + (mb2 + g)     * 144 + (koff + 8 + 2*tq) * 2);
            al[3] = *(const unsigned*)(Pl + (mb2 + g + 8) * 144 + (koff + 8 + 2*tq) * 2);
            #pragma unroll
            for (int nt = 0; nt < 8; nt++) {
                const char* xrow_h = Xh + (nt * 8 + g) * 144 + (koff + 2*tq) * 2;
                const char* xrow_l = Xl + (nt * 8 + g) * 144 + (koff + 2*tq) * 2;
                unsigned bh0 = *(const unsigned*)(xrow_h);
                unsigned bh1 = *(const unsigned*)(xrow_h + 16);
                unsigned bl0 = *(const unsigned*)(xrow_l);
                unsigned bl1 = *(const unsigned*)(xrow_l + 16);
                mma16816(c[nt], ah, bh0, bh1);
                mma16816(c[nt], ah, bl0, bl1);
                mma16816(c[nt], al, bh0, bh1);
            }
        }

        // chunk max of raw u
        float bm = -3.4e38f;
        #pragma unroll
        for (int nt = 0; nt < 8; nt++)
            bm = fmaxf(bm, fmaxf(fmaxf(c[nt][0], c[nt][1]), fmaxf(c[nt][2], c[nt][3])));
        #pragma unroll
        for (int o = 16; o; o >>= 1) bm = fmaxf(bm, __shfl_xor_sync(0xffffffffu, bm, o));
        if (lane == 0) red[w] = bm;
        __syncthreads();                 // also guards sq + proj MMA smem reads
        float Mb = red[0];
        #pragma unroll
        for (int r2 = 1; r2 < 16; r2++) Mb = fmaxf(Mb, red[r2]);

        // online rescale
        float Mn = fmaxf(Mr, Mb);
        float rsc = fexp(Mr - Mn);
        #pragma unroll
        for (int mt = 0; mt < 2; mt++)
            #pragma unroll
            for (int dt = 0; dt < 5; dt++)
                #pragma unroll
                for (int j = 0; j < 4; j++) c2[mt][dt][j] *= rsc;
        Mr = Mn;

        // epilogue: E = exp(u - diag - Mr) -> Eh/El fp16 pair stores (tok-contiguous)
        #pragma unroll
        for (int nt = 0; nt < 8; nt++) {
            int tok0 = nt * 8 + 2 * tq;
            float a0 = fmaf(sq[tok0],     DIAGC, Mr);
            float a1 = fmaf(sq[tok0 + 1], DIAGC, Mr);
            {
                float e0 = fexp(c[nt][0] - a0);
                float e1 = fexp(c[nt][1] - a1);
                unsigned ph, pl;
                split2h(e0, e1, ph, pl);
                *(unsigned*)(Eh + (mb2 + g) * 144 + tok0 * 2) = ph;
                *(unsigned*)(El + (mb2 + g) * 144 + tok0 * 2) = pl;
            }
            {
                float e2 = fexp(c[nt][2] - a0);
                float e3 = fexp(c[nt][3] - a1);
                unsigned ph, pl;
                split2h(e2, e3, ph, pl);
                *(unsigned*)(Eh + (mb2 + g + 8) * 144 + tok0 * 2) = ph;
                *(unsigned*)(El + (mb2 + g + 8) * 144 + tok0 * 2) = pl;
            }
        }
        __syncthreads();

        // kv MMA fp16 3-term: c2 += (Eh+El)*Vh + Eh*Vl, warp tile 32m x 40d
        #pragma unroll
        for (int k = 0; k < 4; k++) {
            const int koff = k * 16;
            unsigned ah[2][4], al[2][4];
            #pragma unroll
            for (int mt = 0; mt < 2; mt++) {
                int r0 = mg + mt * 16 + g, r1 = r0 + 8;
                ah[mt][0] = *(const unsigned*)(Eh + r0 * 144 + (koff + 2*tq) * 2);
                ah[mt][1] = *(const unsigned*)(Eh + r1 * 144 + (koff + 2*tq) * 2);
                ah[mt][2] = *(const unsigned*)(Eh + r0 * 144 + (koff + 8 + 2*tq) * 2);
                ah[mt][3] = *(const unsigned*)(Eh + r1 * 144 + (koff + 8 + 2*tq) * 2);
                al[mt][0] = *(const unsigned*)(El + r0 * 144 + (koff + 2*tq) * 2);
                al[mt][1] = *(const unsigned*)(El + r1 * 144 + (koff + 2*tq) * 2);
                al[mt][2] = *(const unsigned*)(El + r0 * 144 + (koff + 8 + 2*tq) * 2);
                al[mt][3] = *(const unsigned*)(El + r1 * 144 + (koff + 8 + 2*tq) * 2);
            }
            #pragma unroll
            for (int dt = 0; dt < 5; dt++) {
                const char* rh = Vh + (dgr + dt * 8 + g) * 144 + (koff + 2*tq) * 2;
                const char* rl = Vl + (dgr + dt * 8 + g) * 144 + (koff + 2*tq) * 2;
                unsigned bh0 = *(const unsigned*)(rh);
                unsigned bh1 = *(const unsigned*)(rh + 16);
                unsigned bl0 = *(const unsigned*)(rl);
                unsigned bl1 = *(const unsigned*)(rl + 16);
                #pragma unroll
                for (int mt = 0; mt < 2; mt++) {
                    mma16816h(c2[mt][dt], ah[mt], bh0, bh1);
                    mma16816h(c2[mt][dt], al[mt], bh0, bh1);
                    mma16816h(c2[mt][dt], ah[mt], bl0, bl1);
                }
            }
        }
    }

    if (t == 0) g_smax[head * 16 + slice] = Mr;

    // write partials [d][m]
    float* dst = g_kvpart + (size_t)(head * 16 + slice) * 20480;
    #pragma unroll
    for (int mt = 0; mt < 2; mt++) {
        int m0 = mg + mt * 16 + g, m1 = m0 + 8;
        #pragma unroll
        for (int dt = 0; dt < 5; dt++) {
            int d0 = dgr + dt * 8 + 2 * tq;
            dst[d0 * 256 + m0]       = c2[mt][dt][0];
            dst[(d0 + 1) * 256 + m0] = c2[mt][dt][1];
            dst[d0 * 256 + m1]       = c2[mt][dt][2];
            dst[(d0 + 1) * 256 + m1] = c2[mt][dt][3];
        }
    }
}

// ---------------- K2: reduce partials (rescale per slice) -> fp16 kv^T hi/lo
__global__ void k_reduce()
{
    int idx = blockIdx.x * 256 + threadIdx.x;   // < 32*80*256 = 655360
    int h = idx / 20480;
    int rem = idx - h * 20480;
    int d = rem >> 8;
    float Mh = g_smax[h * 16];
    #pragma unroll
    for (int sl = 1; sl < 16; sl++) Mh = fmaxf(Mh, g_smax[h * 16 + sl]);
    float s = 0.0f;
    #pragma unroll
    for (int sl = 0; sl < 16; sl++) {
        float sc = fexp(g_smax[h * 16 + sl] - Mh);
        s = fmaf(g_kvpart[(size_t)(h * 16 + sl) * 20480 + rem], sc, s);
    }
    float corr = (d < 64) ? REPS * g_vsum[h * 64 + d]
               : (d == 64 ? REPS * 8192.0f : 0.0f);
    float val = fmaf(RATIO, s, corr);
    __half hi = __float2half(val);
    g_kvth[idx] = hi;
    g_kvtl[idx] = __float2half(val - __half2float(hi));
}

// ---------------- K3 (fused): query proj + phi + out GEMM + divide ---------
// grid (64, 32), block 512 (16 warps). 128 tokens per block.
// phi_q fp16 hi/lo; kv fp16 hi/lo; out MMA fp16 3-term. Proj stays bf16 3-term.
#define QF_AH   0
#define QF_AL   18432
#define QF_PH   36864
#define QF_PL   73728
#define QF_QH   0          /* phase B: [128 tok][264 fp16] 528 B rows (reuses A/P) */
#define QF_QL   67584
#define QF_KH   135168     /* [80 d][264 fp16] hi */
#define QF_KL   177408     /* lo */
#define QF_SQP  219648
#define QF_SQ   221696
#define QF_SMAX 222208
#define QF_SN   223232
#define QF_SMEM 223744

__global__ void __launch_bounds__(512, 1) k_out_fused(const float* __restrict__ query,
                                                      float* __restrict__ out)
{
    extern __shared__ char smem[];
    char* Ah = smem + QF_AH;    // [128 tok][72 bf16] (144 B rows)
    char* Al = smem + QF_AL;
    char* Ph = smem + QF_PH;    // [256 feat][72 bf16]
    char* Pl = smem + QF_PL;
    char* Qh = smem + QF_QH;    // phase B, fp16 planes
    char* Ql = smem + QF_QL;
    char* Kh = smem + QF_KH;    // fp16 hi
    char* Kl = smem + QF_KL;    // fp16 lo
    float* sqp  = (float*)(smem + QF_SQP);   // [128][4]
    float* sq   = (float*)(smem + QF_SQ);    // [128]
    float* smax = (float*)(smem + QF_SMAX);  // [2][128]
    float* sn   = (float*)(smem + QF_SN);    // [128]

    const int t = threadIdx.x;
    const int head = blockIdx.y;
    const int n0 = blockIdx.x * 128;

    // stage kv^T fp16 hi/lo FIRST (LDGs issue earliest; disjoint from phase A)
    if (t < 320) {
        int row = t >> 2, q = t & 3;
        const uint4* sh = (const uint4*)(g_kvth + ((size_t)head * 80 + row) * 256 + q * 64);
        const uint4* sl = (const uint4*)(g_kvtl + ((size_t)head * 80 + row) * 256 + q * 64);
        uint4* dh = (uint4*)(Kh + row * 528 + q * 128);
        uint4* dl = (uint4*)(Kl + row * 528 + q * 128);
        #pragma unroll
        for (int j = 0; j < 8; j++) { dh[j] = sh[j]; dl[j] = sl[j]; }
    }
    // stage query chunk -> Ah/Al + partial sumsq
    {
        const int tok = t & 127, dblk = t >> 7;   // 4 dblks of 16 d
        const float* xp = query + (size_t)head * Dd * Nn + n0 + tok;
        float s = 0.0f;
        #pragma unroll
        for (int i = 0; i < 8; i++) {
            int d = dblk * 16 + 2 * i;
            float v0 = xp[(size_t)d * Nn];
            float v1 = xp[(size_t)(d + 1) * Nn];
            s = fmaf(v0, v0, fmaf(v1, v1, s));
            unsigned ph, pl;
            split2(v0, v1, ph, pl);
            *(unsigned*)(Ah + tok * 144 + d * 2) = ph;
            *(unsigned*)(Al + tok * 144 + d * 2) = pl;
        }
        sqp[tok * 4 + dblk] = s;
    }
    // stage P
    #pragma unroll
    for (int cc = 0; cc < 4; cc++) {
        int e = t + 512 * cc;           // < 2048
        int row = e >> 3, j = e & 7;
        *(uint4*)(Ph + row * 144 + j * 16) = ((const uint4*)g_pbh)[e];
        *(uint4*)(Pl + row * 144 + j * 16) = ((const uint4*)g_pbl)[e];
    }
    __syncthreads();
    if (t < 128) sq[t] = sqp[4*t] + sqp[4*t+1] + sqp[4*t+2] + sqp[4*t+3];

    const int w = t >> 5, lane = t & 31;
    const int g = lane >> 2, tq = lane & 3;
    const int tb = (w & 7) * 16;            // proj: token base (0..112)
    const int fb = (w >> 3) * 128;          // proj: feature base
    const int tl0 = tb + g, tl1 = tb + g + 8;

    // proj MMA (bf16 3-term, unchanged)
    float c[16][4];
    #pragma unroll
    for (int nt = 0; nt < 16; nt++)
        #pragma unroll
        for (int j = 0; j < 4; j++) c[nt][j] = 0.0f;

    #pragma unroll
    for (int k = 0; k < 4; k++) {
        const int koff = k * 16;
        unsigned ah[4], al[4];
        ah[0] = *(const unsigned*)(Ah + (tb + g)     * 144 + (koff + 2*tq) * 2);
        ah[1] = *(const unsigned*)(Ah + (tb + g + 8) * 144 + (koff + 2*tq) * 2);
        ah[2] = *(const unsigned*)(Ah + (tb + g)     * 144 + (koff + 8 + 2*tq) * 2);
        ah[3] = *(const unsigned*)(Ah + (tb + g + 8) * 144 + (koff + 8 + 2*tq) * 2);
        al[0] = *(const unsigned*)(Al + (tb + g)     * 144 + (koff + 2*tq) * 2);
        al[1] = *(const unsigned*)(Al + (tb + g + 8) * 144 + (koff + 2*tq) * 2);
        al[2] = *(const unsigned*)(Al + (tb + g)     * 144 + (koff + 8 + 2*tq) * 2);
        al[3] = *(const unsigned*)(Al + (tb + g + 8) * 144 + (koff + 8 + 2*tq) * 2);
        #pragma unroll
        for (int nt = 0; nt < 16; nt++) {
            const char* prow_h = Ph + (fb + nt * 8 + g) * 144 + (koff + 2*tq) * 2;
            const char* prow_l = Pl + (fb + nt * 8 + g) * 144 + (koff + 2*tq) * 2;
            unsigned bh0 = *(const unsigned*)(prow_h);
            unsigned bh1 = *(const unsigned*)(prow_h + 16);
            unsigned bl0 = *(const unsigned*)(prow_l);
            unsigned bl1 = *(const unsigned*)(prow_l + 16);
            mma16816(c[nt], ah, bh0, bh1);
            mma16816(c[nt], ah, bl0, bl1);
            mma16816(c[nt], al, bh0, bh1);
        }
    }

    // per-token max over features (two feature-halves combined via smem)
    {
        float m0 = -3.4e38f, m1 = -3.4e38f;
        #pragma unroll
        for (int nt = 0; nt < 16; nt++) {
            m0 = fmaxf(m0, fmaxf(c[nt][0], c[nt][1]));
            m1 = fmaxf(m1, fmaxf(c[nt][2], c[nt][3]));
        }
        m0 = fmaxf(m0, __shfl_xor_sync(0xffffffffu, m0, 1));
        m0 = fmaxf(m0, __shfl_xor_sync(0xffffffffu, m0, 2));
        m1 = fmaxf(m1, __shfl_xor_sync(0xffffffffu, m1, 1));
        m1 = fmaxf(m1, __shfl_xor_sync(0xffffffffu, m1, 2));
        if (tq == 0) {
            smax[(w >> 3) * 128 + tl0] = m0;
            smax[(w >> 3) * 128 + tl1] = m1;
        }
    }
    __syncthreads();   // proj MMA smem reads done; smax/sq ready

    // epilogue: phi_q -> Qh/Ql fp16 split (pairs along m)
    {
        const float dg0 = sq[tl0] * DIAGC;
        const float dg1 = sq[tl1] * DIAGC;
        const float cc0 = -dg0 - fmaxf(smax[tl0], smax[128 + tl0]);
        const float cc1 = -dg1 - fmaxf(smax[tl1], smax[128 + tl1]);
        unsigned* Qh32 = (unsigned*)Qh;   // rows of 132 u32 (528 B)
        unsigned* Ql32 = (unsigned*)Ql;
        #pragma unroll
        for (int nt = 0; nt < 16; nt++) {
            int m = fb + nt * 8 + 2 * tq;
            float p0 = RATIO * fexp(c[nt][0] + cc0) + REPS;
            float p1 = RATIO * fexp(c[nt][1] + cc0) + REPS;
            float p2 = RATIO * fexp(c[nt][2] + cc1) + REPS;
            float p3 = RATIO * fexp(c[nt][3] + cc1) + REPS;
            unsigned ph, pl;
            split2h(p0, p1, ph, pl);
            Qh32[tl0 * 132 + (m >> 1)] = ph;
            Ql32[tl0 * 132 + (m >> 1)] = pl;
            split2h(p2, p3, ph, pl);
            Qh32[tl1 * 132 + (m >> 1)] = ph;
            Ql32[tl1 * 132 + (m >> 1)] = pl;
        }
    }
    __syncthreads();

    // out MMA fp16 3-term: 16 warps, warp tile 16 tok x 40 d, k = 256 (m)
    const int tg = (w & 7) * 16;
    const int dgr = (w >> 3) * 40;

    float co[5][4];
    #pragma unroll
    for (int dt = 0; dt < 5; dt++)
        #pragma unroll
        for (int j = 0; j < 4; j++) co[dt][j] = 0.0f;

    #pragma unroll
    for (int kc = 0; kc < 16; kc++) {
        const int koff = kc * 16;
        unsigned ah[4], al[4];
        ah[0] = *(const unsigned*)(Qh + (tg + g)     * 528 + (koff + 2*tq) * 2);
        ah[1] = *(const unsigned*)(Qh + (tg + g + 8) * 528 + (koff + 2*tq) * 2);
        ah[2] = *(const unsigned*)(Qh + (tg + g)     * 528 + (koff + 8 + 2*tq) * 2);
        ah[3] = *(const unsigned*)(Qh + (tg + g + 8) * 528 + (koff + 8 + 2*tq) * 2);
        al[0] = *(const unsigned*)(Ql + (tg + g)     * 528 + (koff + 2*tq) * 2);
        al[1] = *(const unsigned*)(Ql + (tg + g + 8) * 528 + (koff + 2*tq) * 2);
        al[2] = *(const unsigned*)(Ql + (tg + g)     * 528 + (koff + 8 + 2*tq) * 2);
        al[3] = *(const unsigned*)(Ql + (tg + g + 8) * 528 + (koff + 8 + 2*tq) * 2);
        #pragma unroll
        for (int dt = 0; dt < 5; dt++) {
            const char* rh = Kh + (dgr + dt * 8 + g) * 528 + (koff + 2*tq) * 2;
            const char* rl = Kl + (dgr + dt * 8 + g) * 528 + (koff + 2*tq) * 2;
            unsigned bh0 = *(const unsigned*)(rh);
            unsigned bh1 = *(const unsigned*)(rh + 16);
            unsigned bl0 = *(const unsigned*)(rl);
            unsigned bl1 = *(const unsigned*)(rl + 16);
            mma16816h(co[dt], ah, bh0, bh1);
            mma16816h(co[dt], al, bh0, bh1);
            mma16816h(co[dt], ah, bl0, bl1);
        }
    }

    // norm column (d = 64): warps with dgr=40, dt=3, tq==0
    if (dgr == 40 && tq == 0) {
        sn[tg + g]     = co[3][0];
        sn[tg + g + 8] = co[3][2];
    }
    __syncthreads();
    const float rn0 = 1.0f / sn[tg + g];
    const float rn1 = 1.0f / sn[tg + g + 8];

    float* op = out + (size_t)head * Dd * Nn + n0;
    #pragma unroll
    for (int dt = 0; dt < 5; dt++) {
        int d0 = dgr + dt * 8 + 2 * tq;
        if (d0 < 64) {
            op[(size_t)d0 * Nn + tg + g]           = co[dt][0] * rn0;
            op[(size_t)(d0 + 1) * Nn + tg + g]     = co[dt][1] * rn0;
            op[(size_t)d0 * Nn + tg + g + 8]       = co[dt][2] * rn1;
            op[(size_t)(d0 + 1) * Nn + tg + g + 8] = co[dt][3] * rn1;
        }
    }
}

// ---------------- launch ----------------
extern "C" void kernel_launch(void* const* d_in, const int* in_sizes, int n_in,
                              void* d_out, int out_size)
{
    const float* query = (const float*)d_in[0];
    const float* key   = (const float*)d_in[1];
    const float* value = (const float*)d_in[2];
    const float* proj  = (const float*)d_in[3];
    float* out = (float*)d_out;

    cudaFuncSetAttribute(k_kv_fused,  cudaFuncAttributeMaxDynamicSharedMemorySize, KF_SMEM);
    cudaFuncSetAttribute(k_out_fused, cudaFuncAttributeMaxDynamicSharedMemorySize, QF_SMEM);

    k_init<<<64, 256>>>(proj);
    k_vsum<<<dim3(64, 32), 256>>>(value);
    k_kv_fused<<<dim3(16, 32), 512, KF_SMEM>>>(key, value);
    k_reduce<<<2560, 256>>>();
    k_out_fused<<<dim3(64, 32), 512, QF_SMEM>>>(query, out);
}

// round 16
// speedup vs baseline: 1.0026x; 1.0026x over previous
#include <cuda_runtime.h>
#include <cuda_bf16.h>
#include <cuda_fp16.h>
#include <math.h>

#define Dd 64
#define Nn 8192
#define Mm 256
#define NH 32
#define DN     0.3535533905932738f   /* 64^-0.25 */
#define RATIO  0.0625f               /* 256^-0.5 */
#define REPS   6.25e-8f              /* RATIO * 1e-6 */
#define DIAGC  0.0625f               /* DN^2 * 0.5 */
#define LN_SE  8.317766166719343f    /* 12*ln2 : E scaled by 2^12 for fp16 range */
#define INV_SE 2.44140625e-4f        /* 2^-12 */
#define SQRAT  4096.0f               /* 2^16 * RATIO  (phi_q scale, self-cancelling) */
#define SQEPS  0.004096f             /* 2^16 * REPS */

typedef unsigned long long u64;

// ---------------- scratch (device globals; no allocation) ----------------
__device__ float g_smax[NH * 16];                       // per (head, slice) max raw u
__device__ float g_vsum[NH * 64];                       // R[h][d] = sum_n V
__device__ float g_kvpart[(size_t)NH * 16 * 80 * 256];  // [h*16+sl][d][m], scale 2^12*exp(-Mr_sl)
__device__ __half g_kvth[(size_t)NH * 80 * 256];        // kv^T fp16 hi, [h][d][m] (d=64 -> knorm)
__device__ __half g_kvtl[(size_t)NH * 80 * 256];        // kv^T fp16 lo
__device__ __align__(16) __nv_bfloat16 g_pbh[256 * 64]; // proj*DN hi, [m][d]
__device__ __align__(16) __nv_bfloat16 g_pbl[256 * 64]; // proj*DN lo

// exp on MUFU (FMUL + MUFU.EX2)
static __device__ __forceinline__ float fexp(float x) { return __expf(x); }

// HMMA m16n8k16 bf16 -> fp32 accum
static __device__ __forceinline__ void mma16816(float c[4], const unsigned a[4],
                                                unsigned b0, unsigned b1) {
    asm volatile(
        "mma.sync.aligned.m16n8k16.row.col.f32.bf16.bf16.f32 "
        "{%0,%1,%2,%3}, {%4,%5,%6,%7}, {%8,%9}, {%0,%1,%2,%3};"
        : "+f"(c[0]), "+f"(c[1]), "+f"(c[2]), "+f"(c[3])
        : "r"(a[0]), "r"(a[1]), "r"(a[2]), "r"(a[3]), "r"(b0), "r"(b1));
}
// HMMA m16n8k16 fp16 -> fp32 accum
static __device__ __forceinline__ void mma16816h(float c[4], const unsigned a[4],
                                                 unsigned b0, unsigned b1) {
    asm volatile(
        "mma.sync.aligned.m16n8k16.row.col.f32.f16.f16.f32 "
        "{%0,%1,%2,%3}, {%4,%5,%6,%7}, {%8,%9}, {%0,%1,%2,%3};"
        : "+f"(c[0]), "+f"(c[1]), "+f"(c[2]), "+f"(c[3])
        : "r"(a[0]), "r"(a[1]), "r"(a[2]), "r"(a[3]), "r"(b0), "r"(b1));
}

static __device__ __forceinline__ unsigned h2u(__half2 h) {
    return *reinterpret_cast<unsigned*>(&h);
}

// bf16 hi/lo split, packing pairs (v0,v1) -> (hi-pair, lo-pair)
static __device__ __forceinline__ void split2(float v0, float v1, unsigned& ph, unsigned& pl) {
    __nv_bfloat16 h0 = __float2bfloat16(v0);
    __nv_bfloat16 h1 = __float2bfloat16(v1);
    __nv_bfloat16 l0 = __float2bfloat16(v0 - __bfloat162float(h0));
    __nv_bfloat16 l1 = __float2bfloat16(v1 - __bfloat162float(h1));
    ph = ((unsigned)__bfloat16_as_ushort(h1) << 16) | __bfloat16_as_ushort(h0);
    pl = ((unsigned)__bfloat16_as_ushort(l1) << 16) | __bfloat16_as_ushort(l0);
}
// fp16 hi/lo split of a pair
static __device__ __forceinline__ void split2h(float v0, float v1, unsigned& ph, unsigned& pl) {
    __half2 h = __float22half2_rn(make_float2(v0, v1));
    float2 hf = __half22float2(h);
    __half2 l = __float22half2_rn(make_float2(v0 - hf.x, v1 - hf.y));
    ph = h2u(h);  pl = h2u(l);
}

// ---------------- K0: bf16-split scaled proj ----------------
__global__ void k_init(const float* __restrict__ proj)
{
    int idx = blockIdx.x * 256 + threadIdx.x;   // 64 blocks x 256
    if (idx < 256 * 64) {
        float v = proj[idx] * DN;               // [m][d] layout preserved
        __nv_bfloat16 h = __float2bfloat16(v);
        g_pbh[idx] = h;
        g_pbl[idx] = __float2bfloat16(v - __bfloat162float(h));
    }
}

// ---------------- K_vsum: R[h][d] = sum_n V ----------------
__global__ void k_vsum(const float* __restrict__ value)
{
    __shared__ float red[8];
    const int h = blockIdx.y, d = blockIdx.x, t = threadIdx.x;
    const float4* src = (const float4*)(value + ((size_t)h * 64 + d) * Nn);
    float s = 0.0f;
    #pragma unroll
    for (int i = 0; i < 8; i++) {
        float4 v = src[t + 256 * i];
        s += (v.x + v.y) + (v.z + v.w);
    }
    #pragma unroll
    for (int o = 16; o; o >>= 1) s += __shfl_xor_sync(0xffffffffu, s, o);
    if ((t & 31) == 0) red[t >> 5] = s;
    __syncthreads();
    if (t == 0) {
        float r = 0.0f;
        #pragma unroll
        for (int w2 = 0; w2 < 8; w2++) r += red[w2];
        g_vsum[h * 64 + d] = r;
    }
}

// ---------------- K1 (fused): key proj + exp + kv accumulation -------------
// grid (16 slices, 32 heads), block 512 (16 warps).
// proj MMA swapped: A = P (m rows), B = x (tok rows) -> u[m][tok], bf16 3-term.
// E' = 2^12 * exp(u-diag-Mr) fp16 hi/lo (range-safe), V fp16 hi/lo.
// kv MMA fp16 3-term (EhVh + ElVh + EhVl).
#define KF_XH   0
#define KF_XL   9216
#define KF_PH   18432
#define KF_PL   55296
#define KF_EH   92160
#define KF_EL   129024
#define KF_VH   165888
#define KF_VL   177408
#define KF_SQP  188928
#define KF_SQ   190976
#define KF_RED  191232
#define KF_SMEM 191296

__global__ void __launch_bounds__(512, 1) k_kv_fused(const float* __restrict__ key,
                                                     const float* __restrict__ value)
{
    extern __shared__ char smem[];
    char* Xh = smem + KF_XH;   // [64 tok][72 bf16] (144 B rows)
    char* Xl = smem + KF_XL;
    char* Ph = smem + KF_PH;   // [256 m][72 bf16]
    char* Pl = smem + KF_PL;
    char* Eh = smem + KF_EH;   // [256 m][64 tok] fp16 hi (144 B rows)
    char* El = smem + KF_EL;   // fp16 lo
    char* Vh = smem + KF_VH;   // [80 d][64 tok] fp16 hi (144 B rows)
    char* Vl = smem + KF_VL;   // fp16 lo
    float* sqp = (float*)(smem + KF_SQP);   // [64][8]
    float* sq  = (float*)(smem + KF_SQ);    // [64]
    float* red = (float*)(smem + KF_RED);   // [16]

    const int t = threadIdx.x;
    const int head = blockIdx.y;
    const int slice = blockIdx.x;

    // stage P once (bf16 planes, the A operand: rows = m)
    #pragma unroll
    for (int cc = 0; cc < 4; cc++) {
        int e = t + 512 * cc;           // < 2048
        int row = e >> 3, j = e & 7;
        *(uint4*)(Ph + row * 144 + j * 16) = ((const uint4*)g_pbh)[e];
        *(uint4*)(Pl + row * 144 + j * 16) = ((const uint4*)g_pbl)[e];
    }
    // V const rows: row 64 = fp16 1.0 hi / 0 lo (knorm), rows 65..79 = 0
    for (int e = t; e < 576; e += 512) {
        int row = 64 + e / 36, col = e % 36;
        ((unsigned*)(Vh + row * 144))[col] = (row == 64 && col < 32) ? 0x3C003C00u : 0u;
        ((unsigned*)(Vl + row * 144))[col] = 0u;
    }

    const int w = t >> 5, lane = t & 31;
    const int g = lane >> 2, tq = lane & 3;
    const int mb2 = w * 16;                 // proj: m base (0..240)
    const int mg = (w & 7) * 32;            // kv: m base (0..224)
    const int dgr = (w >> 3) * 40;          // kv: d base (0 or 40)

    float Mr = -3.0e38f;                    // running slice max of raw u
    float c2[2][5][4];
    #pragma unroll
    for (int mt = 0; mt < 2; mt++)
        #pragma unroll
        for (int dt = 0; dt < 5; dt++)
            #pragma unroll
            for (int j = 0; j < 4; j++) c2[mt][dt][j] = 0.0f;

    const float* kp = key + (size_t)head * Dd * Nn;
    const float* vp = value + (size_t)head * Dd * Nn;

    for (int ch = 0; ch < 8; ch++) {
        const int n0 = slice * 512 + ch * 64;
        __syncthreads();   // prior kv MMA reads of E/V done; prior proj reads of X done

        // stage key chunk -> Xh/Xl + partial sumsq (8 d per thread)
        {
            const int tok = t & 63, dblk = t >> 6;   // dblk in 0..7
            const float* xp = kp + n0 + tok;
            float s = 0.0f;
            #pragma unroll
            for (int i = 0; i < 4; i++) {
                int d = dblk * 8 + 2 * i;
                float v0 = xp[(size_t)d * Nn];
                float v1 = xp[(size_t)(d + 1) * Nn];
                s = fmaf(v0, v0, fmaf(v1, v1, s));
                unsigned ph, pl;
                split2(v0, v1, ph, pl);
                *(unsigned*)(Xh + tok * 144 + d * 2) = ph;
                *(unsigned*)(Xl + tok * 144 + d * 2) = pl;
            }
            sqp[tok * 8 + dblk] = s;
        }
        // stage V chunk rows 0..63 fp16 hi/lo (8 tok per thread)
        {
            int d = t >> 3, q = t & 7;
            const float* src = vp + (size_t)d * Nn + n0 + q * 8;
            float4 va = *(const float4*)(src);
            float4 vb = *(const float4*)(src + 4);
            unsigned h0, l0, h1, l1, h2, l2, h3, l3;
            split2h(va.x, va.y, h0, l0);
            split2h(va.z, va.w, h1, l1);
            split2h(vb.x, vb.y, h2, l2);
            split2h(vb.z, vb.w, h3, l3);
            *(uint4*)(Vh + d * 144 + q * 16) = make_uint4(h0, h1, h2, h3);
            *(uint4*)(Vl + d * 144 + q * 16) = make_uint4(l0, l1, l2, l3);
        }
        __syncthreads();
        if (t < 64) {
            float s = 0.0f;
            #pragma unroll
            for (int j = 0; j < 8; j++) s += sqp[t * 8 + j];
            sq[t] = s;
        }

        // proj MMA (swapped): u[m][tok], warp tile 16 m x 64 tok, bf16 3-term
        float c[8][4];
        #pragma unroll
        for (int nt = 0; nt < 8; nt++)
            #pragma unroll
            for (int j = 0; j < 4; j++) c[nt][j] = 0.0f;

        #pragma unroll
        for (int k = 0; k < 4; k++) {
            const int koff = k * 16;
            unsigned ah[4], al[4];
            ah[0] = *(const unsigned*)(Ph + (mb2 + g)     * 144 + (koff + 2*tq) * 2);
            ah[1] = *(const unsigned*)(Ph + (mb2 + g + 8) * 144 + (koff + 2*tq) * 2);
            ah[2] = *(const unsigned*)(Ph + (mb2 + g)     * 144 + (koff + 8 + 2*tq) * 2);
            ah[3] = *(const unsigned*)(Ph + (mb2 + g + 8) * 144 + (koff + 8 + 2*tq) * 2);
            al[0] = *(const unsigned*)(Pl + (mb2 + g)     * 144 + (koff + 2*tq) * 2);
            al[1] = *(const unsigned*)(Pl + (mb2 + g + 8) * 144 + (koff + 2*tq) * 2);
            al[2] = *(const unsigned*)(Pl + (mb2 + g)     * 144 + (koff + 8 + 2*tq) * 2);
            al[3] = *(const unsigned*)(Pl + (mb2 + g + 8) * 144 + (koff + 8 + 2*tq) * 2);
            #pragma unroll
            for (int nt = 0; nt < 8; nt++) {
                const char* xrow_h = Xh + (nt * 8 + g) * 144 + (koff + 2*tq) * 2;
                const char* xrow_l = Xl + (nt * 8 + g) * 144 + (koff + 2*tq) * 2;
                unsigned bh0 = *(const unsigned*)(xrow_h);
                unsigned bh1 = *(const unsigned*)(xrow_h + 16);
                unsigned bl0 = *(const unsigned*)(xrow_l);
                unsigned bl1 = *(const unsigned*)(xrow_l + 16);
                mma16816(c[nt], ah, bh0, bh1);
                mma16816(c[nt], ah, bl0, bl1);
                mma16816(c[nt], al, bh0, bh1);
            }
        }

        // chunk max of raw u
        float bm = -3.4e38f;
        #pragma unroll
        for (int nt = 0; nt < 8; nt++)
            bm = fmaxf(bm, fmaxf(fmaxf(c[nt][0], c[nt][1]), fmaxf(c[nt][2], c[nt][3])));
        #pragma unroll
        for (int o = 16; o; o >>= 1) bm = fmaxf(bm, __shfl_xor_sync(0xffffffffu, bm, o));
        if (lane == 0) red[w] = bm;
        __syncthreads();                 // also guards sq + proj MMA smem reads
        float Mb = red[0];
        #pragma unroll
        for (int r2 = 1; r2 < 16; r2++) Mb = fmaxf(Mb, red[r2]);

        // online rescale
        float Mn = fmaxf(Mr, Mb);
        float rsc = fexp(Mr - Mn);
        #pragma unroll
        for (int mt = 0; mt < 2; mt++)
            #pragma unroll
            for (int dt = 0; dt < 5; dt++)
                #pragma unroll
                for (int j = 0; j < 4; j++) c2[mt][dt][j] *= rsc;
        Mr = Mn;

        // epilogue: E' = 2^12*exp(u - diag - Mr) -> Eh/El (range-safe fp16)
        const float MrS = Mr - LN_SE;
        #pragma unroll
        for (int nt = 0; nt < 8; nt++) {
            int tok0 = nt * 8 + 2 * tq;
            float a0 = fmaf(sq[tok0],     DIAGC, MrS);
            float a1 = fmaf(sq[tok0 + 1], DIAGC, MrS);
            {
                float e0 = fexp(c[nt][0] - a0);
                float e1 = fexp(c[nt][1] - a1);
                unsigned ph, pl;
                split2h(e0, e1, ph, pl);
                *(unsigned*)(Eh + (mb2 + g) * 144 + tok0 * 2) = ph;
                *(unsigned*)(El + (mb2 + g) * 144 + tok0 * 2) = pl;
            }
            {
                float e2 = fexp(c[nt][2] - a0);
                float e3 = fexp(c[nt][3] - a1);
                unsigned ph, pl;
                split2h(e2, e3, ph, pl);
                *(unsigned*)(Eh + (mb2 + g + 8) * 144 + tok0 * 2) = ph;
                *(unsigned*)(El + (mb2 + g + 8) * 144 + tok0 * 2) = pl;
            }
        }
        __syncthreads();

        // kv MMA fp16 3-term: c2 += (Eh+El)*Vh + Eh*Vl, warp tile 32m x 40d
        #pragma unroll
        for (int k = 0; k < 4; k++) {
            const int koff = k * 16;
            unsigned ah[2][4], al[2][4];
            #pragma unroll
            for (int mt = 0; mt < 2; mt++) {
                int r0 = mg + mt * 16 + g, r1 = r0 + 8;
                ah[mt][0] = *(const unsigned*)(Eh + r0 * 144 + (koff + 2*tq) * 2);
                ah[mt][1] = *(const unsigned*)(Eh + r1 * 144 + (koff + 2*tq) * 2);
                ah[mt][2] = *(const unsigned*)(Eh + r0 * 144 + (koff + 8 + 2*tq) * 2);
                ah[mt][3] = *(const unsigned*)(Eh + r1 * 144 + (koff + 8 + 2*tq) * 2);
                al[mt][0] = *(const unsigned*)(El + r0 * 144 + (koff + 2*tq) * 2);
                al[mt][1] = *(const unsigned*)(El + r1 * 144 + (koff + 2*tq) * 2);
                al[mt][2] = *(const unsigned*)(El + r0 * 144 + (koff + 8 + 2*tq) * 2);
                al[mt][3] = *(const unsigned*)(El + r1 * 144 + (koff + 8 + 2*tq) * 2);
            }
            #pragma unroll
            for (int dt = 0; dt < 5; dt++) {
                const char* rh = Vh + (dgr + dt * 8 + g) * 144 + (koff + 2*tq) * 2;
                const char* rl = Vl + (dgr + dt * 8 + g) * 144 + (koff + 2*tq) * 2;
                unsigned bh0 = *(const unsigned*)(rh);
                unsigned bh1 = *(const unsigned*)(rh + 16);
                unsigned bl0 = *(const unsigned*)(rl);
                unsigned bl1 = *(const unsigned*)(rl + 16);
                #pragma unroll
                for (int mt = 0; mt < 2; mt++) {
                    mma16816h(c2[mt][dt], ah[mt], bh0, bh1);
                    mma16816h(c2[mt][dt], al[mt], bh0, bh1);
                    mma16816h(c2[mt][dt], ah[mt], bl0, bl1);
                }
            }
        }
    }

    if (t == 0) g_smax[head * 16 + slice] = Mr;

    // write partials [d][m] (carry scale 2^12 * exp(-Mr_sl))
    float* dst = g_kvpart + (size_t)(head * 16 + slice) * 20480;
    #pragma unroll
    for (int mt = 0; mt < 2; mt++) {
        int m0 = mg + mt * 16 + g, m1 = m0 + 8;
        #pragma unroll
        for (int dt = 0; dt < 5; dt++) {
            int d0 = dgr + dt * 8 + 2 * tq;
            dst[d0 * 256 + m0]       = c2[mt][dt][0];
            dst[(d0 + 1) * 256 + m0] = c2[mt][dt][1];
            dst[d0 * 256 + m1]       = c2[mt][dt][2];
            dst[(d0 + 1) * 256 + m1] = c2[mt][dt][3];
        }
    }
}

// ---------------- K2: reduce partials (rescale per slice, undo 2^12) -------
__global__ void k_reduce()
{
    int idx = blockIdx.x * 256 + threadIdx.x;   // < 32*80*256 = 655360
    int h = idx / 20480;
    int rem = idx - h * 20480;
    int d = rem >> 8;
    float Mh = g_smax[h * 16];
    #pragma unroll
    for (int sl = 1; sl < 16; sl++) Mh = fmaxf(Mh, g_smax[h * 16 + sl]);
    float s = 0.0f;
    #pragma unroll
    for (int sl = 0; sl < 16; sl++) {
        float sc = fexp(g_smax[h * 16 + sl] - Mh) * INV_SE;
        s = fmaf(g_kvpart[(size_t)(h * 16 + sl) * 20480 + rem], sc, s);
    }
    float corr = (d < 64) ? REPS * g_vsum[h * 64 + d]
               : (d == 64 ? REPS * 8192.0f : 0.0f);
    float val = fmaf(RATIO, s, corr);
    __half hi = __float2half(val);
    g_kvth[idx] = hi;
    g_kvtl[idx] = __float2half(val - __half2float(hi));
}

// ---------------- K3 (fused): query proj + phi + out GEMM + divide ---------
// grid (64, 32), block 512 (16 warps). 128 tokens per block.
// phi' = 2^16*phi (range-safe fp16, scale cancels in the division).
#define QF_AH   0
#define QF_AL   18432
#define QF_PH   36864
#define QF_PL   73728
#define QF_QH   0          /* phase B: [128 tok][264 fp16] 528 B rows (reuses A/P) */
#define QF_QL   67584
#define QF_KH   135168     /* [80 d][264 fp16] hi */
#define QF_KL   177408     /* lo */
#define QF_SQP  219648
#define QF_SQ   221696
#define QF_SMAX 222208
#define QF_SN   223232
#define QF_SMEM 223744

__global__ void __launch_bounds__(512, 1) k_out_fused(const float* __restrict__ query,
                                                      float* __restrict__ out)
{
    extern __shared__ char smem[];
    char* Ah = smem + QF_AH;    // [128 tok][72 bf16] (144 B rows)
    char* Al = smem + QF_AL;
    char* Ph = smem + QF_PH;    // [256 feat][72 bf16]
    char* Pl = smem + QF_PL;
    char* Qh = smem + QF_QH;    // phase B, fp16 planes
    char* Ql = smem + QF_QL;
    char* Kh = smem + QF_KH;    // fp16 hi
    char* Kl = smem + QF_KL;    // fp16 lo
    float* sqp  = (float*)(smem + QF_SQP);   // [128][4]
    float* sq   = (float*)(smem + QF_SQ);    // [128]
    float* smax = (float*)(smem + QF_SMAX);  // [2][128]
    float* sn   = (float*)(smem + QF_SN);    // [128]

    const int t = threadIdx.x;
    const int head = blockIdx.y;
    const int n0 = blockIdx.x * 128;

    // stage kv^T fp16 hi/lo FIRST (LDGs issue earliest; disjoint from phase A)
    if (t < 320) {
        int row = t >> 2, q = t & 3;
        const uint4* sh = (const uint4*)(g_kvth + ((size_t)head * 80 + row) * 256 + q * 64);
        const uint4* sl = (const uint4*)(g_kvtl + ((size_t)head * 80 + row) * 256 + q * 64);
        uint4* dh = (uint4*)(Kh + row * 528 + q * 128);
        uint4* dl = (uint4*)(Kl + row * 528 + q * 128);
        #pragma unroll
        for (int j = 0; j < 8; j++) { dh[j] = sh[j]; dl[j] = sl[j]; }
    }
    // stage query chunk -> Ah/Al + partial sumsq
    {
        const int tok = t & 127, dblk = t >> 7;   // 4 dblks of 16 d
        const float* xp = query + (size_t)head * Dd * Nn + n0 + tok;
        float s = 0.0f;
        #pragma unroll
        for (int i = 0; i < 8; i++) {
            int d = dblk * 16 + 2 * i;
            float v0 = xp[(size_t)d * Nn];
            float v1 = xp[(size_t)(d + 1) * Nn];
            s = fmaf(v0, v0, fmaf(v1, v1, s));
            unsigned ph, pl;
            split2(v0, v1, ph, pl);
            *(unsigned*)(Ah + tok * 144 + d * 2) = ph;
            *(unsigned*)(Al + tok * 144 + d * 2) = pl;
        }
        sqp[tok * 4 + dblk] = s;
    }
    // stage P
    #pragma unroll
    for (int cc = 0; cc < 4; cc++) {
        int e = t + 512 * cc;           // < 2048
        int row = e >> 3, j = e & 7;
        *(uint4*)(Ph + row * 144 + j * 16) = ((const uint4*)g_pbh)[e];
        *(uint4*)(Pl + row * 144 + j * 16) = ((const uint4*)g_pbl)[e];
    }
    __syncthreads();
    if (t < 128) sq[t] = sqp[4*t] + sqp[4*t+1] + sqp[4*t+2] + sqp[4*t+3];

    const int w = t >> 5, lane = t & 31;
    const int g = lane >> 2, tq = lane & 3;
    const int tb = (w & 7) * 16;            // proj: token base (0..112)
    const int fb = (w >> 3) * 128;          // proj: feature base
    const int tl0 = tb + g, tl1 = tb + g + 8;

    // proj MMA (bf16 3-term, unchanged)
    float c[16][4];
    #pragma unroll
    for (int nt = 0; nt < 16; nt++)
        #pragma unroll
        for (int j = 0; j < 4; j++) c[nt][j] = 0.0f;

    #pragma unroll
    for (int k = 0; k < 4; k++) {
        const int koff = k * 16;
        unsigned ah[4], al[4];
        ah[0] = *(const unsigned*)(Ah + (tb + g)     * 144 + (koff + 2*tq) * 2);
        ah[1] = *(const unsigned*)(Ah + (tb + g + 8) * 144 + (koff + 2*tq) * 2);
        ah[2] = *(const unsigned*)(Ah + (tb + g)     * 144 + (koff + 8 + 2*tq) * 2);
        ah[3] = *(const unsigned*)(Ah + (tb + g + 8) * 144 + (koff + 8 + 2*tq) * 2);
        al[0] = *(const unsigned*)(Al + (tb + g)     * 144 + (koff + 2*tq) * 2);
        al[1] = *(const unsigned*)(Al + (tb + g + 8) * 144 + (koff + 2*tq) * 2);
        al[2] = *(const unsigned*)(Al + (tb + g)     * 144 + (koff + 8 + 2*tq) * 2);
        al[3] = *(const unsigned*)(Al + (tb + g + 8) * 144 + (koff + 8 + 2*tq) * 2);
        #pragma unroll
        for (int nt = 0; nt < 16; nt++) {
            const char* prow_h = Ph + (fb + nt * 8 + g) * 144 + (koff + 2*tq) * 2;
            const char* prow_l = Pl + (fb + nt * 8 + g) * 144 + (koff + 2*tq) * 2;
            unsigned bh0 = *(const unsigned*)(prow_h);
            unsigned bh1 = *(const unsigned*)(prow_h + 16);
            unsigned bl0 = *(const unsigned*)(prow_l);
            unsigned bl1 = *(const unsigned*)(prow_l + 16);
            mma16816(c[nt], ah, bh0, bh1);
            mma16816(c[nt], ah, bl0, bl1);
            mma16816(c[nt], al, bh0, bh1);
        }
    }

    // per-token max over features (two feature-halves combined via smem)
    {
        float m0 = -3.4e38f, m1 = -3.4e38f;
        #pragma unroll
        for (int nt = 0; nt < 16; nt++) {
            m0 = fmaxf(m0, fmaxf(c[nt][0], c[nt][1]));
            m1 = fmaxf(m1, fmaxf(c[nt][2], c[nt][3]));
        }
        m0 = fmaxf(m0, __shfl_xor_sync(0xffffffffu, m0, 1));
        m0 = fmaxf(m0, __shfl_xor_sync(0xffffffffu, m0, 2));
        m1 = fmaxf(m1, __shfl_xor_sync(0xffffffffu, m1, 1));
        m1 = fmaxf(m1, __shfl_xor_sync(0xffffffffu, m1, 2));
        if (tq == 0) {
            smax[(w >> 3) * 128 + tl0] = m0;
            smax[(w >> 3) * 128 + tl1] = m1;
        }
    }
    __syncthreads();   // proj MMA smem reads done; smax/sq ready

    // epilogue: phi' = 2^16*phi -> Qh/Ql fp16 split (pairs along m)
    {
        const float dg0 = sq[tl0] * DIAGC;
        const float dg1 = sq[tl1] * DIAGC;
        const float cc0 = -dg0 - fmaxf(smax[tl0], smax[128 + tl0]);
        const float cc1 = -dg1 - fmaxf(smax[tl1], smax[128 + tl1]);
        unsigned* Qh32 = (unsigned*)Qh;   // rows of 132 u32 (528 B)
        unsigned* Ql32 = (unsigned*)Ql;
        #pragma unroll
        for (int nt = 0; nt < 16; nt++) {
            int m = fb + nt * 8 + 2 * tq;
            float p0 = SQRAT * fexp(c[nt][0] + cc0) + SQEPS;
            float p1 = SQRAT * fexp(c[nt][1] + cc0) + SQEPS;
            float p2 = SQRAT * fexp(c[nt][2] + cc1) + SQEPS;
            float p3 = SQRAT * fexp(c[nt][3] + cc1) + SQEPS;
            unsigned ph, pl;
            split2h(p0, p1, ph, pl);
            Qh32[tl0 * 132 + (m >> 1)] = ph;
            Ql32[tl0 * 132 + (m >> 1)] = pl;
            split2h(p2, p3, ph, pl);
            Qh32[tl1 * 132 + (m >> 1)] = ph;
            Ql32[tl1 * 132 + (m >> 1)] = pl;
        }
    }
    __syncthreads();

    // out MMA fp16 3-term: 16 warps, warp tile 16 tok x 40 d, k = 256 (m)
    const int tg = (w & 7) * 16;
    const int dgr = (w >> 3) * 40;

    float co[5][4];
    #pragma unroll
    for (int dt = 0; dt < 5; dt++)
        #pragma unroll
        for (int j = 0; j < 4; j++) co[dt][j] = 0.0f;

    #pragma unroll
    for (int kc = 0; kc < 16; kc++) {
        const int koff = kc * 16;
        unsigned ah[4], al[4];
        ah[0] = *(const unsigned*)(Qh + (tg + g)     * 528 + (koff + 2*tq) * 2);
        ah[1] = *(const unsigned*)(Qh + (tg + g + 8) * 528 + (koff + 2*tq) * 2);
        ah[2] = *(const unsigned*)(Qh + (tg + g)     * 528 + (koff + 8 + 2*tq) * 2);
        ah[3] = *(const unsigned*)(Qh + (tg + g + 8) * 528 + (koff + 8 + 2*tq) * 2);
        al[0] = *(const unsigned*)(Ql + (tg + g)     * 528 + (koff + 2*tq) * 2);
        al[1] = *(const unsigned*)(Ql + (tg + g + 8) * 528 + (koff + 2*tq) * 2);
        al[2] = *(const unsigned*)(Ql + (tg + g)     * 528 + (koff + 8 + 2*tq) * 2);
        al[3] = *(const unsigned*)(Ql + (tg + g + 8) * 528 + (koff + 8 + 2*tq) * 2);
        #pragma unroll
        for (int dt = 0; dt < 5; dt++) {
            const char* rh = Kh + (dgr + dt * 8 + g) * 528 + (koff + 2*tq) * 2;
            const char* rl = Kl + (dgr + dt * 8 + g) * 528 + (koff + 2*tq) * 2;
            unsigned bh0 = *(const unsigned*)(rh);
            unsigned bh1 = *(const unsigned*)(rh + 16);
            unsigned bl0 = *(const unsigned*)(rl);
            unsigned bl1 = *(const unsigned*)(rl + 16);
            mma16816h(co[dt], ah, bh0, bh1);
            mma16816h(co[dt], al, bh0, bh1);
            mma16816h(co[dt], ah, bl0, bl1);
        }
    }

    // norm column (d = 64): warps with dgr=40, dt=3, tq==0
    if (dgr == 40 && tq == 0) {
        sn[tg + g]     = co[3][0];
        sn[tg + g + 8] = co[3][2];
    }
    __syncthreads();
    const float rn0 = 1.0f / sn[tg + g];       // 2^16 scale cancels in ratio
    const float rn1 = 1.0f / sn[tg + g + 8];

    float* op = out + (size_t)head * Dd * Nn + n0;
    #pragma unroll
    for (int dt = 0; dt < 5; dt++) {
        int d0 = dgr + dt * 8 + 2 * tq;
        if (d0 < 64) {
            op[(size_t)d0 * Nn + tg + g]           = co[dt][0] * rn0;
            op[(size_t)(d0 + 1) * Nn + tg + g]     = co[dt][1] * rn0;
            op[(size_t)d0 * Nn + tg + g + 8]       = co[dt][2] * rn1;
            op[(size_t)(d0 + 1) * Nn + tg + g + 8] = co[dt][3] * rn1;
        }
    }
}

// ---------------- launch ----------------
extern "C" void kernel_launch(void* const* d_in, const int* in_sizes, int n_in,
                              void* d_out, int out_size)
{
    const float* query = (const float*)d_in[0];
    const float* key   = (const float*)d_in[1];
    const float* value = (const float*)d_in[2];
    const float* proj  = (const float*)d_in[3];
    float* out = (float*)d_out;

    cudaFuncSetAttribute(k_kv_fused,  cudaFuncAttributeMaxDynamicSharedMemorySize, KF_SMEM);
    cudaFuncSetAttribute(k_out_fused, cudaFuncAttributeMaxDynamicSharedMemorySize, QF_SMEM);

    k_init<<<64, 256>>>(proj);
    k_vsum<<<dim3(64, 32), 256>>>(value);
    k_kv_fused<<<dim3(16, 32), 512, KF_SMEM>>>(key, value);
    k_reduce<<<2560, 256>>>();
    k_out_fused<<<dim3(64, 32), 512, QF_SMEM>>>(query, out);
}

// round 17
// speedup vs baseline: 1.2614x; 1.2581x over previous
#include <cuda_runtime.h>
#include <cuda_bf16.h>
#include <cuda_fp16.h>
#include <math.h>

#define Dd 64
#define Nn 8192
#define Mm 256
#define NH 32
#define DN     0.3535533905932738f   /* 64^-0.25 */
#define RATIO  0.0625f               /* 256^-0.5 */
#define REPS   6.25e-8f              /* RATIO * 1e-6 */
#define DIAGC  0.0625f               /* DN^2 * 0.5 */
#define LN_SE  9.704060527839234f    /* 14*ln2 : E scaled by 2^14 for fp16 range */
#define INV_SE 6.103515625e-5f       /* 2^-14 */
#define SQRAT  16384.0f              /* 2^18 * RATIO  (phi_q scale, self-cancelling) */
#define SQEPS  0.016384f             /* 2^18 * REPS */

typedef unsigned long long u64;

// ---------------- scratch (device globals; no allocation) ----------------
__device__ float g_smax[NH * 16];                       // per (head, slice) max raw u
__device__ float g_vsum[NH * 64];                       // R[h][d] = sum_n V
__device__ float g_kvpart[(size_t)NH * 16 * 80 * 256];  // [h*16+sl][d][m], scale 2^14*exp(-Mr_sl)
__device__ __half g_kvt[(size_t)NH * 80 * 256];         // kv^T fp16, [h][d][m] (d=64 -> knorm)
__device__ __align__(16) __nv_bfloat16 g_pbh[256 * 64]; // proj*DN hi, [m][d]
__device__ __align__(16) __nv_bfloat16 g_pbl[256 * 64]; // proj*DN lo

// exp on MUFU (FMUL + MUFU.EX2)
static __device__ __forceinline__ float fexp(float x) { return __expf(x); }

// HMMA m16n8k16 bf16 -> fp32 accum
static __device__ __forceinline__ void mma16816(float c[4], const unsigned a[4],
                                                unsigned b0, unsigned b1) {
    asm volatile(
        "mma.sync.aligned.m16n8k16.row.col.f32.bf16.bf16.f32 "
        "{%0,%1,%2,%3}, {%4,%5,%6,%7}, {%8,%9}, {%0,%1,%2,%3};"
        : "+f"(c[0]), "+f"(c[1]), "+f"(c[2]), "+f"(c[3])
        : "r"(a[0]), "r"(a[1]), "r"(a[2]), "r"(a[3]), "r"(b0), "r"(b1));
}
// HMMA m16n8k16 fp16 -> fp32 accum
static __device__ __forceinline__ void mma16816h(float c[4], const unsigned a[4],
                                                 unsigned b0, unsigned b1) {
    asm volatile(
        "mma.sync.aligned.m16n8k16.row.col.f32.f16.f16.f32 "
        "{%0,%1,%2,%3}, {%4,%5,%6,%7}, {%8,%9}, {%0,%1,%2,%3};"
        : "+f"(c[0]), "+f"(c[1]), "+f"(c[2]), "+f"(c[3])
        : "r"(a[0]), "r"(a[1]), "r"(a[2]), "r"(a[3]), "r"(b0), "r"(b1));
}

static __device__ __forceinline__ unsigned h2u(__half2 h) {
    return *reinterpret_cast<unsigned*>(&h);
}

// bf16 hi/lo split, packing pairs (v0,v1) -> (hi-pair, lo-pair)
static __device__ __forceinline__ void split2(float v0, float v1, unsigned& ph, unsigned& pl) {
    __nv_bfloat16 h0 = __float2bfloat16(v0);
    __nv_bfloat16 h1 = __float2bfloat16(v1);
    __nv_bfloat16 l0 = __float2bfloat16(v0 - __bfloat162float(h0));
    __nv_bfloat16 l1 = __float2bfloat16(v1 - __bfloat162float(h1));
    ph = ((unsigned)__bfloat16_as_ushort(h1) << 16) | __bfloat16_as_ushort(h0);
    pl = ((unsigned)__bfloat16_as_ushort(l1) << 16) | __bfloat16_as_ushort(l0);
}
// fp16 hi/lo split of a pair
static __device__ __forceinline__ void split2h(float v0, float v1, unsigned& ph, unsigned& pl) {
    __half2 h = __float22half2_rn(make_float2(v0, v1));
    float2 hf = __half22float2(h);
    __half2 l = __float22half2_rn(make_float2(v0 - hf.x, v1 - hf.y));
    ph = h2u(h);  pl = h2u(l);
}

// ---------------- K0: bf16-split scaled proj ----------------
__global__ void k_init(const float* __restrict__ proj)
{
    int idx = blockIdx.x * 256 + threadIdx.x;   // 64 blocks x 256
    if (idx < 256 * 64) {
        float v = proj[idx] * DN;               // [m][d] layout preserved
        __nv_bfloat16 h = __float2bfloat16(v);
        g_pbh[idx] = h;
        g_pbl[idx] = __float2bfloat16(v - __bfloat162float(h));
    }
}

// ---------------- K_vsum: R[h][d] = sum_n V ----------------
__global__ void k_vsum(const float* __restrict__ value)
{
    __shared__ float red[8];
    const int h = blockIdx.y, d = blockIdx.x, t = threadIdx.x;
    const float4* src = (const float4*)(value + ((size_t)h * 64 + d) * Nn);
    float s = 0.0f;
    #pragma unroll
    for (int i = 0; i < 8; i++) {
        float4 v = src[t + 256 * i];
        s += (v.x + v.y) + (v.z + v.w);
    }
    #pragma unroll
    for (int o = 16; o; o >>= 1) s += __shfl_xor_sync(0xffffffffu, s, o);
    if ((t & 31) == 0) red[t >> 5] = s;
    __syncthreads();
    if (t == 0) {
        float r = 0.0f;
        #pragma unroll
        for (int w2 = 0; w2 < 8; w2++) r += red[w2];
        g_vsum[h * 64 + d] = r;
    }
}

// ---------------- K1 (fused): key proj + exp + kv accumulation -------------
// grid (16 slices, 32 heads), block 512 (16 warps).
// proj: A = P (m rows), B = x (tok rows) -> u[m][tok], bf16 3-term.
// E' = 2^14*exp(u-diag-Mr) fp16 hi/lo; V single fp16; kv MMA fp16 2-term.
// Register prefetch: chunk ch+1 global loads overlap chunk ch compute.
#define KF_XH   0
#define KF_XL   9216
#define KF_PH   18432
#define KF_PL   55296
#define KF_EH   92160
#define KF_EL   129024
#define KF_VH   165888
#define KF_SQP  177408
#define KF_SQ   179456
#define KF_RED  179712
#define KF_SMEM 179776

__global__ void __launch_bounds__(512, 1) k_kv_fused(const float* __restrict__ key,
                                                     const float* __restrict__ value)
{
    extern __shared__ char smem[];
    char* Xh = smem + KF_XH;   // [64 tok][72 bf16] (144 B rows)
    char* Xl = smem + KF_XL;
    char* Ph = smem + KF_PH;   // [256 m][72 bf16]
    char* Pl = smem + KF_PL;
    char* Eh = smem + KF_EH;   // [256 m][64 tok] fp16 hi (144 B rows)
    char* El = smem + KF_EL;   // fp16 lo
    char* Vh = smem + KF_VH;   // [80 d][64 tok] fp16 (144 B rows)
    float* sqp = (float*)(smem + KF_SQP);   // [64][8]
    float* sq  = (float*)(smem + KF_SQ);    // [64]
    float* red = (float*)(smem + KF_RED);   // [16]

    const int t = threadIdx.x;
    const int head = blockIdx.y;
    const int slice = blockIdx.x;

    // stage P once (bf16 planes, the A operand: rows = m)
    #pragma unroll
    for (int cc = 0; cc < 4; cc++) {
        int e = t + 512 * cc;           // < 2048
        int row = e >> 3, j = e & 7;
        *(uint4*)(Ph + row * 144 + j * 16) = ((const uint4*)g_pbh)[e];
        *(uint4*)(Pl + row * 144 + j * 16) = ((const uint4*)g_pbl)[e];
    }
    // V const rows: row 64 = fp16 1.0 (knorm), rows 65..79 = 0
    for (int e = t; e < 576; e += 512) {
        int row = 64 + e / 36, col = e % 36;
        ((unsigned*)(Vh + row * 144))[col] = (row == 64) ? 0x3C003C00u : 0u;
    }

    const int w = t >> 5, lane = t & 31;
    const int g = lane >> 2, tq = lane & 3;
    const int mb2 = w * 16;                 // proj: m base (0..240)
    const int mg = (w & 7) * 32;            // kv: m base (0..224)
    const int dgr = (w >> 3) * 40;          // kv: d base (0 or 40)
    const int toki = t & 63, dblk = t >> 6; // key staging coords
    const int vd = t >> 3, vq = t & 7;      // V staging coords

    float Mr = -3.0e38f;                    // running slice max of raw u
    float c2[2][5][4];
    #pragma unroll
    for (int mt = 0; mt < 2; mt++)
        #pragma unroll
        for (int dt = 0; dt < 5; dt++)
            #pragma unroll
            for (int j = 0; j < 4; j++) c2[mt][dt][j] = 0.0f;

    const float* kp = key + (size_t)head * Dd * Nn;
    const float* vp = value + (size_t)head * Dd * Nn;

    // prefetch chunk 0
    float pk[8], pv[8];
    {
        const int n0 = slice * 512;
        const float* xp = kp + n0 + toki;
        #pragma unroll
        for (int i = 0; i < 8; i++) pk[i] = xp[(size_t)(dblk * 8 + i) * Nn];
        const float* src = vp + (size_t)vd * Nn + n0 + vq * 8;
        *(float4*)(pv)     = *(const float4*)(src);
        *(float4*)(pv + 4) = *(const float4*)(src + 4);
    }

    for (int ch = 0; ch < 8; ch++) {
        __syncthreads();   // prior kv MMA reads of E/V done; prior proj reads of X done

        // stage key chunk from regs -> Xh/Xl + partial sumsq
        {
            float s = 0.0f;
            #pragma unroll
            for (int i = 0; i < 4; i++) {
                float v0 = pk[2 * i], v1 = pk[2 * i + 1];
                s = fmaf(v0, v0, fmaf(v1, v1, s));
                unsigned ph, pl;
                split2(v0, v1, ph, pl);
                int d = dblk * 8 + 2 * i;
                *(unsigned*)(Xh + toki * 144 + d * 2) = ph;
                *(unsigned*)(Xl + toki * 144 + d * 2) = pl;
            }
            sqp[toki * 8 + dblk] = s;
        }
        // stage V chunk from regs -> Vh single fp16
        {
            __half2 x0 = __float22half2_rn(make_float2(pv[0], pv[1]));
            __half2 x1 = __float22half2_rn(make_float2(pv[2], pv[3]));
            __half2 x2 = __float22half2_rn(make_float2(pv[4], pv[5]));
            __half2 x3 = __float22half2_rn(make_float2(pv[6], pv[7]));
            *(uint4*)(Vh + vd * 144 + vq * 16) = make_uint4(h2u(x0), h2u(x1), h2u(x2), h2u(x3));
        }
        // prefetch chunk ch+1 (LDGs overlap all compute below)
        if (ch < 7) {
            const int n1 = slice * 512 + (ch + 1) * 64;
            const float* xp = kp + n1 + toki;
            #pragma unroll
            for (int i = 0; i < 8; i++) pk[i] = xp[(size_t)(dblk * 8 + i) * Nn];
            const float* src = vp + (size_t)vd * Nn + n1 + vq * 8;
            *(float4*)(pv)     = *(const float4*)(src);
            *(float4*)(pv + 4) = *(const float4*)(src + 4);
        }
        __syncthreads();
        if (t < 64) {
            float s = 0.0f;
            #pragma unroll
            for (int j = 0; j < 8; j++) s += sqp[t * 8 + j];
            sq[t] = s;
        }

        // proj MMA (swapped): u[m][tok], warp tile 16 m x 64 tok, bf16 3-term
        float c[8][4];
        #pragma unroll
        for (int nt = 0; nt < 8; nt++)
            #pragma unroll
            for (int j = 0; j < 4; j++) c[nt][j] = 0.0f;

        #pragma unroll
        for (int k = 0; k < 4; k++) {
            const int koff = k * 16;
            unsigned ah[4], al[4];
            ah[0] = *(const unsigned*)(Ph + (mb2 + g)     * 144 + (koff + 2*tq) * 2);
            ah[1] = *(const unsigned*)(Ph + (mb2 + g + 8) * 144 + (koff + 2*tq) * 2);
            ah[2] = *(const unsigned*)(Ph + (mb2 + g)     * 144 + (koff + 8 + 2*tq) * 2);
            ah[3] = *(const unsigned*)(Ph + (mb2 + g + 8) * 144 + (koff + 8 + 2*tq) * 2);
            al[0] = *(const unsigned*)(Pl + (mb2 + g)     * 144 + (koff + 2*tq) * 2);
            al[1] = *(const unsigned*)(Pl + (mb2 + g + 8) * 144 + (koff + 2*tq) * 2);
            al[2] = *(const unsigned*)(Pl + (mb2 + g)     * 144 + (koff + 8 + 2*tq) * 2);
            al[3] = *(const unsigned*)(Pl + (mb2 + g + 8) * 144 + (koff + 8 + 2*tq) * 2);
            #pragma unroll
            for (int nt = 0; nt < 8; nt++) {
                const char* xrow_h = Xh + (nt * 8 + g) * 144 + (koff + 2*tq) * 2;
                const char* xrow_l = Xl + (nt * 8 + g) * 144 + (koff + 2*tq) * 2;
                unsigned bh0 = *(const unsigned*)(xrow_h);
                unsigned bh1 = *(const unsigned*)(xrow_h + 16);
                unsigned bl0 = *(const unsigned*)(xrow_l);
                unsigned bl1 = *(const unsigned*)(xrow_l + 16);
                mma16816(c[nt], ah, bh0, bh1);
                mma16816(c[nt], ah, bl0, bl1);
                mma16816(c[nt], al, bh0, bh1);
            }
        }

        // chunk max of raw u
        float bm = -3.4e38f;
        #pragma unroll
        for (int nt = 0; nt < 8; nt++)
            bm = fmaxf(bm, fmaxf(fmaxf(c[nt][0], c[nt][1]), fmaxf(c[nt][2], c[nt][3])));
        #pragma unroll
        for (int o = 16; o; o >>= 1) bm = fmaxf(bm, __shfl_xor_sync(0xffffffffu, bm, o));
        if (lane == 0) red[w] = bm;
        __syncthreads();                 // also guards sq + proj MMA smem reads
        float Mb = red[0];
        #pragma unroll
        for (int r2 = 1; r2 < 16; r2++) Mb = fmaxf(Mb, red[r2]);

        // online rescale
        float Mn = fmaxf(Mr, Mb);
        float rsc = fexp(Mr - Mn);
        #pragma unroll
        for (int mt = 0; mt < 2; mt++)
            #pragma unroll
            for (int dt = 0; dt < 5; dt++)
                #pragma unroll
                for (int j = 0; j < 4; j++) c2[mt][dt][j] *= rsc;
        Mr = Mn;

        // epilogue: E' = 2^14*exp(u - diag - Mr) -> Eh/El (range-safe fp16)
        const float MrS = Mr - LN_SE;
        #pragma unroll
        for (int nt = 0; nt < 8; nt++) {
            int tok0 = nt * 8 + 2 * tq;
            float a0 = fmaf(sq[tok0],     DIAGC, MrS);
            float a1 = fmaf(sq[tok0 + 1], DIAGC, MrS);
            {
                float e0 = fexp(c[nt][0] - a0);
                float e1 = fexp(c[nt][1] - a1);
                unsigned ph, pl;
                split2h(e0, e1, ph, pl);
                *(unsigned*)(Eh + (mb2 + g) * 144 + tok0 * 2) = ph;
                *(unsigned*)(El + (mb2 + g) * 144 + tok0 * 2) = pl;
            }
            {
                float e2 = fexp(c[nt][2] - a0);
                float e3 = fexp(c[nt][3] - a1);
                unsigned ph, pl;
                split2h(e2, e3, ph, pl);
                *(unsigned*)(Eh + (mb2 + g + 8) * 144 + tok0 * 2) = ph;
                *(unsigned*)(El + (mb2 + g + 8) * 144 + tok0 * 2) = pl;
            }
        }
        __syncthreads();

        // kv MMA fp16 2-term: c2 += (Eh+El)*Vh, warp tile 32m x 40d
        #pragma unroll
        for (int k = 0; k < 4; k++) {
            const int koff = k * 16;
            unsigned ah[2][4], al[2][4];
            #pragma unroll
            for (int mt = 0; mt < 2; mt++) {
                int r0 = mg + mt * 16 + g, r1 = r0 + 8;
                ah[mt][0] = *(const unsigned*)(Eh + r0 * 144 + (koff + 2*tq) * 2);
                ah[mt][1] = *(const unsigned*)(Eh + r1 * 144 + (koff + 2*tq) * 2);
                ah[mt][2] = *(const unsigned*)(Eh + r0 * 144 + (koff + 8 + 2*tq) * 2);
                ah[mt][3] = *(const unsigned*)(Eh + r1 * 144 + (koff + 8 + 2*tq) * 2);
                al[mt][0] = *(const unsigned*)(El + r0 * 144 + (koff + 2*tq) * 2);
                al[mt][1] = *(const unsigned*)(El + r1 * 144 + (koff + 2*tq) * 2);
                al[mt][2] = *(const unsigned*)(El + r0 * 144 + (koff + 8 + 2*tq) * 2);
                al[mt][3] = *(const unsigned*)(El + r1 * 144 + (koff + 8 + 2*tq) * 2);
            }
            #pragma unroll
            for (int dt = 0; dt < 5; dt++) {
                const char* rh = Vh + (dgr + dt * 8 + g) * 144 + (koff + 2*tq) * 2;
                unsigned b0 = *(const unsigned*)(rh);
                unsigned b1 = *(const unsigned*)(rh + 16);
                #pragma unroll
                for (int mt = 0; mt < 2; mt++) {
                    mma16816h(c2[mt][dt], ah[mt], b0, b1);
                    mma16816h(c2[mt][dt], al[mt], b0, b1);
                }
            }
        }
    }

    if (t == 0) g_smax[head * 16 + slice] = Mr;

    // write partials [d][m] (carry scale 2^14 * exp(-Mr_sl))
    float* dst = g_kvpart + (size_t)(head * 16 + slice) * 20480;
    #pragma unroll
    for (int mt = 0; mt < 2; mt++) {
        int m0 = mg + mt * 16 + g, m1 = m0 + 8;
        #pragma unroll
        for (int dt = 0; dt < 5; dt++) {
            int d0 = dgr + dt * 8 + 2 * tq;
            dst[d0 * 256 + m0]       = c2[mt][dt][0];
            dst[(d0 + 1) * 256 + m0] = c2[mt][dt][1];
            dst[d0 * 256 + m1]       = c2[mt][dt][2];
            dst[(d0 + 1) * 256 + m1] = c2[mt][dt][3];
        }
    }
}

// ---------------- K2: reduce partials (rescale per slice, undo 2^14) -------
__global__ void k_reduce()
{
    int idx = blockIdx.x * 256 + threadIdx.x;   // < 32*80*256 = 655360
    int h = idx / 20480;
    int rem = idx - h * 20480;
    int d = rem >> 8;
    float Mh = g_smax[h * 16];
    #pragma unroll
    for (int sl = 1; sl < 16; sl++) Mh = fmaxf(Mh, g_smax[h * 16 + sl]);
    float s = 0.0f;
    #pragma unroll
    for (int sl = 0; sl < 16; sl++) {
        float sc = fexp(g_smax[h * 16 + sl] - Mh) * INV_SE;
        s = fmaf(g_kvpart[(size_t)(h * 16 + sl) * 20480 + rem], sc, s);
    }
    float corr = (d < 64) ? REPS * g_vsum[h * 64 + d]
               : (d == 64 ? REPS * 8192.0f : 0.0f);
    float val = fmaf(RATIO, s, corr);
    g_kvt[idx] = __float2half(val);
}

// ---------------- K3 (fused): query proj + phi + out GEMM + divide ---------
// grid (64, 32), block 512 (16 warps). 128 tokens per block.
// phi' = 2^18*phi fp16 hi/lo (range-safe, scale cancels); kv single fp16.
// out MMA fp16 2-term.
#define QF_AH   0
#define QF_AL   18432
#define QF_PH   36864
#define QF_PL   73728
#define QF_QH   0          /* phase B: [128 tok][264 fp16] 528 B rows (reuses A/P) */
#define QF_QL   67584
#define QF_KH   135168     /* [80 d][264 fp16] single plane */
#define QF_SQP  177408
#define QF_SQ   179456
#define QF_SMAX 179968
#define QF_SN   180992
#define QF_SMEM 181504

__global__ void __launch_bounds__(512, 1) k_out_fused(const float* __restrict__ query,
                                                      float* __restrict__ out)
{
    extern __shared__ char smem[];
    char* Ah = smem + QF_AH;    // [128 tok][72 bf16] (144 B rows)
    char* Al = smem + QF_AL;
    char* Ph = smem + QF_PH;    // [256 feat][72 bf16]
    char* Pl = smem + QF_PL;
    char* Qh = smem + QF_QH;    // phase B, fp16 planes
    char* Ql = smem + QF_QL;
    char* Kh = smem + QF_KH;    // fp16 single
    float* sqp  = (float*)(smem + QF_SQP);   // [128][4]
    float* sq   = (float*)(smem + QF_SQ);    // [128]
    float* smax = (float*)(smem + QF_SMAX);  // [2][128]
    float* sn   = (float*)(smem + QF_SN);    // [128]

    const int t = threadIdx.x;
    const int head = blockIdx.y;
    const int n0 = blockIdx.x * 128;

    // stage kv^T fp16 FIRST (LDGs issue earliest; disjoint from phase A)
    if (t < 320) {
        int row = t >> 2, q = t & 3;
        const uint4* src = (const uint4*)(g_kvt + ((size_t)head * 80 + row) * 256 + q * 64);
        uint4* dst = (uint4*)(Kh + row * 528 + q * 128);
        #pragma unroll
        for (int j = 0; j < 8; j++) dst[j] = src[j];
    }
    // stage query chunk -> Ah/Al + partial sumsq
    {
        const int tok = t & 127, dblk = t >> 7;   // 4 dblks of 16 d
        const float* xp = query + (size_t)head * Dd * Nn + n0 + tok;
        float s = 0.0f;
        #pragma unroll
        for (int i = 0; i < 8; i++) {
            int d = dblk * 16 + 2 * i;
            float v0 = xp[(size_t)d * Nn];
            float v1 = xp[(size_t)(d + 1) * Nn];
            s = fmaf(v0, v0, fmaf(v1, v1, s));
            unsigned ph, pl;
            split2(v0, v1, ph, pl);
            *(unsigned*)(Ah + tok * 144 + d * 2) = ph;
            *(unsigned*)(Al + tok * 144 + d * 2) = pl;
        }
        sqp[tok * 4 + dblk] = s;
    }
    // stage P
    #pragma unroll
    for (int cc = 0; cc < 4; cc++) {
        int e = t + 512 * cc;           // < 2048
        int row = e >> 3, j = e & 7;
        *(uint4*)(Ph + row * 144 + j * 16) = ((const uint4*)g_pbh)[e];
        *(uint4*)(Pl + row * 144 + j * 16) = ((const uint4*)g_pbl)[e];
    }
    __syncthreads();
    if (t < 128) sq[t] = sqp[4*t] + sqp[4*t+1] + sqp[4*t+2] + sqp[4*t+3];

    const int w = t >> 5, lane = t & 31;
    const int g = lane >> 2, tq = lane & 3;
    const int tb = (w & 7) * 16;            // proj: token base (0..112)
    const int fb = (w >> 3) * 128;          // proj: feature base
    const int tl0 = tb + g, tl1 = tb + g + 8;

    // proj MMA (bf16 3-term, unchanged)
    float c[16][4];
    #pragma unroll
    for (int nt = 0; nt < 16; nt++)
        #pragma unroll
        for (int j = 0; j < 4; j++) c[nt][j] = 0.0f;

    #pragma unroll
    for (int k = 0; k < 4; k++) {
        const int koff = k * 16;
        unsigned ah[4], al[4];
        ah[0] = *(const unsigned*)(Ah + (tb + g)     * 144 + (koff + 2*tq) * 2);
        ah[1] = *(const unsigned*)(Ah + (tb + g + 8) * 144 + (koff + 2*tq) * 2);
        ah[2] = *(const unsigned*)(Ah + (tb + g)     * 144 + (koff + 8 + 2*tq) * 2);
        ah[3] = *(const unsigned*)(Ah + (tb + g + 8) * 144 + (koff + 8 + 2*tq) * 2);
        al[0] = *(const unsigned*)(Al + (tb + g)     * 144 + (koff + 2*tq) * 2);
        al[1] = *(const unsigned*)(Al + (tb + g + 8) * 144 + (koff + 2*tq) * 2);
        al[2] = *(const unsigned*)(Al + (tb + g)     * 144 + (koff + 8 + 2*tq) * 2);
        al[3] = *(const unsigned*)(Al + (tb + g + 8) * 144 + (koff + 8 + 2*tq) * 2);
        #pragma unroll
        for (int nt = 0; nt < 16; nt++) {
            const char* prow_h = Ph + (fb + nt * 8 + g) * 144 + (koff + 2*tq) * 2;
            const char* prow_l = Pl + (fb + nt * 8 + g) * 144 + (koff + 2*tq) * 2;
            unsigned bh0 = *(const unsigned*)(prow_h);
            unsigned bh1 = *(const unsigned*)(prow_h + 16);
            unsigned bl0 = *(const unsigned*)(prow_l);
            unsigned bl1 = *(const unsigned*)(prow_l + 16);
            mma16816(c[nt], ah, bh0, bh1);
            mma16816(c[nt], ah, bl0, bl1);
            mma16816(c[nt], al, bh0, bh1);
        }
    }

    // per-token max over features (two feature-halves combined via smem)
    {
        float m0 = -3.4e38f, m1 = -3.4e38f;
        #pragma unroll
        for (int nt = 0; nt < 16; nt++) {
            m0 = fmaxf(m0, fmaxf(c[nt][0], c[nt][1]));
            m1 = fmaxf(m1, fmaxf(c[nt][2], c[nt][3]));
        }
        m0 = fmaxf(m0, __shfl_xor_sync(0xffffffffu, m0, 1));
        m0 = fmaxf(m0, __shfl_xor_sync(0xffffffffu, m0, 2));
        m1 = fmaxf(m1, __shfl_xor_sync(0xffffffffu, m1, 1));
        m1 = fmaxf(m1, __shfl_xor_sync(0xffffffffu, m1, 2));
        if (tq == 0) {
            smax[(w >> 3) * 128 + tl0] = m0;
            smax[(w >> 3) * 128 + tl1] = m1;
        }
    }
    __syncthreads();   // proj MMA smem reads done; smax/sq ready

    // epilogue: phi' = 2^18*phi -> Qh/Ql fp16 split (pairs along m)
    {
        const float dg0 = sq[tl0] * DIAGC;
        const float dg1 = sq[tl1] * DIAGC;
        const float cc0 = -dg0 - fmaxf(smax[tl0], smax[128 + tl0]);
        const float cc1 = -dg1 - fmaxf(smax[tl1], smax[128 + tl1]);
        unsigned* Qh32 = (unsigned*)Qh;   // rows of 132 u32 (528 B)
        unsigned* Ql32 = (unsigned*)Ql;
        #pragma unroll
        for (int nt = 0; nt < 16; nt++) {
            int m = fb + nt * 8 + 2 * tq;
            float p0 = SQRAT * fexp(c[nt][0] + cc0) + SQEPS;
            float p1 = SQRAT * fexp(c[nt][1] + cc0) + SQEPS;
            float p2 = SQRAT * fexp(c[nt][2] + cc1) + SQEPS;
            float p3 = SQRAT * fexp(c[nt][3] + cc1) + SQEPS;
            unsigned ph, pl;
            split2h(p0, p1, ph, pl);
            Qh32[tl0 * 132 + (m >> 1)] = ph;
            Ql32[tl0 * 132 + (m >> 1)] = pl;
            split2h(p2, p3, ph, pl);
            Qh32[tl1 * 132 + (m >> 1)] = ph;
            Ql32[tl1 * 132 + (m >> 1)] = pl;
        }
    }
    __syncthreads();

    // out MMA fp16 2-term: 16 warps, warp tile 16 tok x 40 d, k = 256 (m)
    const int tg = (w & 7) * 16;
    const int dgr = (w >> 3) * 40;

    float co[5][4];
    #pragma unroll
    for (int dt = 0; dt < 5; dt++)
        #pragma unroll
        for (int j = 0; j < 4; j++) co[dt][j] = 0.0f;

    #pragma unroll
    for (int kc = 0; kc < 16; kc++) {
        const int koff = kc * 16;
        unsigned ah[4], al[4];
        ah[0] = *(const unsigned*)(Qh + (tg + g)     * 528 + (koff + 2*tq) * 2);
        ah[1] = *(const unsigned*)(Qh + (tg + g + 8) * 528 + (koff + 2*tq) * 2);
        ah[2] = *(const unsigned*)(Qh + (tg + g)     * 528 + (koff + 8 + 2*tq) * 2);
        ah[3] = *(const unsigned*)(Qh + (tg + g + 8) * 528 + (koff + 8 + 2*tq) * 2);
        al[0] = *(const unsigned*)(Ql + (tg + g)     * 528 + (koff + 2*tq) * 2);
        al[1] = *(const unsigned*)(Ql + (tg + g + 8) * 528 + (koff + 2*tq) * 2);
        al[2] = *(const unsigned*)(Ql + (tg + g)     * 528 + (koff + 8 + 2*tq) * 2);
        al[3] = *(const unsigned*)(Ql + (tg + g + 8) * 528 + (koff + 8 + 2*tq) * 2);
        #pragma unroll
        for (int dt = 0; dt < 5; dt++) {
            const char* rh = Kh + (dgr + dt * 8 + g) * 528 + (koff + 2*tq) * 2;
            unsigned b0 = *(const unsigned*)(rh);
            unsigned b1 = *(const unsigned*)(rh + 16);
            mma16816h(co[dt], ah, b0, b1);
            mma16816h(co[dt], al, b0, b1);
        }
    }

    // norm column (d = 64): warps with dgr=40, dt=3, tq==0
    if (dgr == 40 && tq == 0) {
        sn[tg + g]     = co[3][0];
        sn[tg + g + 8] = co[3][2];
    }
    __syncthreads();
    const float rn0 = 1.0f / sn[tg + g];       // 2^18 scale cancels in ratio
    const float rn1 = 1.0f / sn[tg + g + 8];

    float* op = out + (size_t)head * Dd * Nn + n0;
    #pragma unroll
    for (int dt = 0; dt < 5; dt++) {
        int d0 = dgr + dt * 8 + 2 * tq;
        if (d0 < 64) {
            op[(size_t)d0 * Nn + tg + g]           = co[dt][0] * rn0;
            op[(size_t)(d0 + 1) * Nn + tg + g]     = co[dt][1] * rn0;
            op[(size_t)d0 * Nn + tg + g + 8]       = co[dt][2] * rn1;
            op[(size_t)(d0 + 1) * Nn + tg + g + 8] = co[dt][3] * rn1;
        }
    }
}

// ---------------- launch ----------------
extern "C" void kernel_launch(void* const* d_in, const int* in_sizes, int n_in,
                              void* d_out, int out_size)
{
    const float* query = (const float*)d_in[0];
    const float* key   = (const float*)d_in[1];
    const float* value = (const float*)d_in[2];
    const float* proj  = (const float*)d_in[3];
    float* out = (float*)d_out;

    cudaFuncSetAttribute(k_kv_fused,  cudaFuncAttributeMaxDynamicSharedMemorySize, KF_SMEM);
    cudaFuncSetAttribute(k_out_fused, cudaFuncAttributeMaxDynamicSharedMemorySize, QF_SMEM);

    k_init<<<64, 256>>>(proj);
    k_vsum<<<dim3(64, 32), 256>>>(value);
    k_kv_fused<<<dim3(16, 32), 512, KF_SMEM>>>(key, value);
    k_reduce<<<2560, 256>>>();
    k_out_fused<<<dim3(64, 32), 512, QF_SMEM>>>(query, out);
}